// round 2
// baseline (speedup 1.0000x reference)
#include <cuda_runtime.h>
#include <math.h>

#define NTOK 8192
#define DIM  1024
#define FFN  4096
#define NE   10

// ---------------- scratch (device globals: no allocation allowed) ----------
__device__ float g_A [(size_t)NTOK * FFN];   // gelu(x@W1+b1) activations
__device__ float g_H [(size_t)NTOK * DIM];   // h = A@W2 + b2 + x
__device__ float g_Xg[(size_t)NTOK * DIM];   // x gathered into expert order
__device__ int   g_perm[NTOK];
__device__ int   g_cnt[NE];
__device__ int   g_off[NE];
__device__ int   g_cur[NE];

// ---------------- routing ---------------------------------------------------
__global__ void k_zero() {
    int i = threadIdx.x;
    if (i < NE) { g_cnt[i] = 0; g_cur[i] = 0; }
}

__global__ void k_count(const int* __restrict__ ids) {
    int i = blockIdx.x * blockDim.x + threadIdx.x;
    if (i < NTOK) atomicAdd(&g_cnt[ids[i]], 1);
}

__global__ void k_scan() {
    if (threadIdx.x == 0) {
        int s = 0;
        for (int e = 0; e < NE; e++) { g_off[e] = s; s += g_cnt[e]; }
    }
}

__global__ void k_scatter(const int* __restrict__ ids) {
    int i = blockIdx.x * blockDim.x + threadIdx.x;
    if (i < NTOK) {
        int e = ids[i];
        int p = g_off[e] + atomicAdd(&g_cur[e], 1);
        g_perm[p] = i;
    }
}

__global__ void k_gather(const float* __restrict__ x) {
    int p   = blockIdx.x;
    int src = g_perm[p];
    const float4* s = (const float4*)(x + (size_t)src * DIM);
    float4*       d = (float4*)(g_Xg + (size_t)p * DIM);
    d[threadIdx.x] = s[threadIdx.x];   // 256 threads * float4 = 1024 floats
}

// ---------------- fused GEMM ------------------------------------------------
// MODE 0: C = gelu(A@B + bias)               -> g_A      (A = x or g_Xg)
// MODE 1: C = A@B + bias + xres              -> g_H      (A = g_A)
// MODE 2: g = sigmoid(A@B + bias); out = g*h + (1-g)*x   (A = x or g_Xg)
//         shared: Fout[row] = v ; domain: Fout[perm[row]] += v
template <int MODE, bool DOMAIN>
__global__ void __launch_bounds__(256, 2) gemm_k(
    const float* __restrict__ xin,      // x (shared path); domain path uses g_Xg
    const float* __restrict__ Bbase,    // weight base (domain: + e*K*Nd)
    const float* __restrict__ biasBase, // bias base   (domain: + e*Nd)
    float*       __restrict__ Fout,     // final output (MODE 2 only)
    int K, int Nd)
{
    int e = 0, Mloc = NTOK, rowBase = 0;
    if (DOMAIN) {
        e       = blockIdx.z;
        Mloc    = g_cnt[e];
        rowBase = g_off[e];
        if ((int)blockIdx.y * 128 >= Mloc) return;   // empty tile -> bail fast
    }

    const float* A;
    if (MODE == 1) A = g_A + (size_t)rowBase * K;
    else           A = (DOMAIN ? g_Xg : xin) + (size_t)rowBase * K;
    const float* B    = Bbase    + (DOMAIN ? (size_t)e * K * Nd : 0);
    const float* bias = biasBase + (DOMAIN ? (size_t)e * Nd     : 0);
    const float* Xr   = DOMAIN ? g_Xg : xin;   // residual / gate mix source

    __shared__ float As[8][128];
    __shared__ float Bs[8][128];

    int tid = threadIdx.x;
    int tx = tid & 15, ty = tid >> 4;

    // A tile load map: 1 float4 per thread, transpose into As[k][m]
    int am = tid >> 1;            // 0..127 (row in tile)
    int ak = (tid & 1) * 4;       // 0 or 4 (k offset)
    // B tile load map: coalesced float4, Bs[k][n]
    int bk = tid >> 5;            // 0..7
    int bn = (tid & 31) * 4;      // 0..124

    int rowTile = blockIdx.y * 128;
    int colTile = blockIdx.x * 128;

    bool aValid = (rowTile + am) < Mloc;
    const float* Aptr = A + (size_t)(rowTile + am) * K + ak;
    const float* Bptr = B + (size_t)bk * Nd + colTile + bn;

    float acc[8][8];
#pragma unroll
    for (int i = 0; i < 8; i++)
#pragma unroll
        for (int j = 0; j < 8; j++) acc[i][j] = 0.f;

    for (int kk = 0; kk < K; kk += 8) {
        float4 av = aValid ? *(const float4*)Aptr : make_float4(0.f, 0.f, 0.f, 0.f);
        float4 bv = *(const float4*)Bptr;

        As[ak + 0][am] = av.x;
        As[ak + 1][am] = av.y;
        As[ak + 2][am] = av.z;
        As[ak + 3][am] = av.w;
        *(float4*)&Bs[bk][bn] = bv;
        __syncthreads();

#pragma unroll
        for (int k = 0; k < 8; k++) {
            float a[8], b[8];
            *(float4*)(a)     = *(const float4*)&As[k][ty * 8];
            *(float4*)(a + 4) = *(const float4*)&As[k][ty * 8 + 4];
            *(float4*)(b)     = *(const float4*)&Bs[k][tx * 8];
            *(float4*)(b + 4) = *(const float4*)&Bs[k][tx * 8 + 4];
#pragma unroll
            for (int i = 0; i < 8; i++)
#pragma unroll
                for (int j = 0; j < 8; j++)
                    acc[i][j] = fmaf(a[i], b[j], acc[i][j]);
        }
        Aptr += 8;
        Bptr += (size_t)8 * Nd;
        __syncthreads();
    }

    // ---------------- epilogue ----------------
    int col0 = colTile + tx * 8;
#pragma unroll
    for (int i = 0; i < 8; i++) {
        int lr = rowTile + ty * 8 + i;
        if (lr >= Mloc) continue;
        int grow = rowBase + lr;               // row in (permuted) activation space

        if (MODE == 0) {
            float* dst = g_A + (size_t)grow * Nd + col0;
#pragma unroll
            for (int j = 0; j < 8; j++) {
                float v = acc[i][j] + bias[col0 + j];
                dst[j] = 0.5f * v * (1.0f + erff(v * 0.70710678118654752f));
            }
        } else if (MODE == 1) {
            float*       dst = g_H + (size_t)grow * Nd + col0;
            const float* r   = Xr  + (size_t)grow * Nd + col0;
#pragma unroll
            for (int j = 0; j < 8; j++)
                dst[j] = acc[i][j] + bias[col0 + j] + r[j];
        } else {
            const float* hp = g_H + (size_t)grow * Nd + col0;
            const float* xp = Xr  + (size_t)grow * Nd + col0;
            int orow = DOMAIN ? g_perm[grow] : grow;
            float* dst = Fout + (size_t)orow * Nd + col0;
#pragma unroll
            for (int j = 0; j < 8; j++) {
                float gl = acc[i][j] + bias[col0 + j];
                float gv = 1.0f / (1.0f + expf(-gl));
                float v  = gv * hp[j] + (1.0f - gv) * xp[j];
                if (DOMAIN) dst[j] += v;       // unique writer per (token,col)
                else        dst[j]  = v;
            }
        }
    }
}

// ---------------- launch -----------------------------------------------------
extern "C" void kernel_launch(void* const* d_in, const int* in_sizes, int n_in,
                              void* d_out, int out_size)
{
    const float* x   = (const float*)d_in[0];
    const int*   ids = (const int*)  d_in[1];
    const float* sW1 = (const float*)d_in[2];
    const float* sb1 = (const float*)d_in[3];
    const float* sW2 = (const float*)d_in[4];
    const float* sb2 = (const float*)d_in[5];
    const float* sWg = (const float*)d_in[6];
    const float* sbg = (const float*)d_in[7];
    const float* dW1 = (const float*)d_in[8];
    const float* db1 = (const float*)d_in[9];
    const float* dW2 = (const float*)d_in[10];
    const float* db2 = (const float*)d_in[11];
    const float* dWg = (const float*)d_in[12];
    const float* dbg = (const float*)d_in[13];
    float* out = (float*)d_out;

    // routing
    k_zero   <<<1, 32>>>();
    k_count  <<<NTOK / 256, 256>>>(ids);
    k_scan   <<<1, 32>>>();
    k_scatter<<<NTOK / 256, 256>>>(ids);
    k_gather <<<NTOK, 256>>>(x);

    dim3 blk(256);

    // shared expert (all tokens)
    gemm_k<0, false><<<dim3(FFN / 128, NTOK / 128, 1), blk>>>(x, sW1, sb1, nullptr, DIM, FFN);
    gemm_k<1, false><<<dim3(DIM / 128, NTOK / 128, 1), blk>>>(x, sW2, sb2, nullptr, FFN, DIM);
    gemm_k<2, false><<<dim3(DIM / 128, NTOK / 128, 1), blk>>>(x, sWg, sbg, out,     DIM, DIM);

    // domain experts (grouped over expert buckets; empty tiles exit immediately)
    gemm_k<0, true><<<dim3(FFN / 128, NTOK / 128, NE), blk>>>(nullptr, dW1, db1, nullptr, DIM, FFN);
    gemm_k<1, true><<<dim3(DIM / 128, NTOK / 128, NE), blk>>>(nullptr, dW2, db2, nullptr, FFN, DIM);
    gemm_k<2, true><<<dim3(DIM / 128, NTOK / 128, NE), blk>>>(nullptr, dWg, dbg, out,     DIM, DIM);
}

// round 3
// speedup vs baseline: 2.8451x; 2.8451x over previous
#include <cuda_runtime.h>
#include <math.h>
#include <stdint.h>

#define NTOK 8192
#define DIM  1024
#define FFN  4096
#define NE   10

// ---------------- scratch (device globals: no allocation allowed) ----------
__device__ float g_A [(size_t)NTOK * FFN];   // gelu(x@W1+b1) activations
__device__ float g_H [(size_t)NTOK * DIM];   // h = A@W2 + b2 + x
__device__ float g_Xg[(size_t)NTOK * DIM];   // x gathered into expert order
__device__ int   g_perm[NTOK];
__device__ int   g_cnt[NE];
__device__ int   g_off[NE];
__device__ int   g_cur[NE];

// ---------------- routing ---------------------------------------------------
__global__ void k_zero() {
    int i = threadIdx.x;
    if (i < NE) { g_cnt[i] = 0; g_cur[i] = 0; }
}

__global__ void k_count(const int* __restrict__ ids) {
    int i = blockIdx.x * blockDim.x + threadIdx.x;
    if (i < NTOK) atomicAdd(&g_cnt[ids[i]], 1);
}

__global__ void k_scan() {
    if (threadIdx.x == 0) {
        int s = 0;
        for (int e = 0; e < NE; e++) { g_off[e] = s; s += g_cnt[e]; }
    }
}

__global__ void k_scatter(const int* __restrict__ ids) {
    int i = blockIdx.x * blockDim.x + threadIdx.x;
    if (i < NTOK) {
        int e = ids[i];
        int p = g_off[e] + atomicAdd(&g_cur[e], 1);
        g_perm[p] = i;
    }
}

__global__ void k_gather(const float* __restrict__ x) {
    int p   = blockIdx.x;
    int src = g_perm[p];
    const float4* s = (const float4*)(x + (size_t)src * DIM);
    float4*       d = (float4*)(g_Xg + (size_t)p * DIM);
    d[threadIdx.x] = s[threadIdx.x];   // 256 threads * float4 = 1024 floats
}

// ---------------- tf32 helpers ----------------------------------------------
__device__ __forceinline__ uint32_t f2tf32(float f) {
    uint32_t r;
    asm("cvt.rna.tf32.f32 %0, %1;" : "=r"(r) : "f"(f));
    return r;
}

__device__ __forceinline__ void mma_tf32(float* c, const uint32_t* a, const uint32_t* b) {
    asm volatile(
        "mma.sync.aligned.m16n8k8.row.col.f32.tf32.tf32.f32 "
        "{%0,%1,%2,%3},{%4,%5,%6,%7},{%8,%9},{%0,%1,%2,%3};"
        : "+f"(c[0]), "+f"(c[1]), "+f"(c[2]), "+f"(c[3])
        : "r"(a[0]), "r"(a[1]), "r"(a[2]), "r"(a[3]), "r"(b[0]), "r"(b[1]));
}

// ---------------- fused tensor-core GEMM -------------------------------------
// BM=128, BN=128, BK=16, 256 threads = 8 warps (2 x 4), warp tile 64x32.
// MODE 0: C = gelu(A@B + bias)               -> g_A
// MODE 1: C = A@B + bias + xres              -> g_H
// MODE 2: g = sigmoid(A@B + bias); out = g*h + (1-g)*x
//         shared: Fout[row] = v ; domain: Fout[perm[row]] += v
template <int MODE, bool DOMAIN>
__global__ void __launch_bounds__(256, 2) gemm_k(
    const float* __restrict__ xin,
    const float* __restrict__ Bbase,
    const float* __restrict__ biasBase,
    float*       __restrict__ Fout,
    int K, int Nd)
{
    int e = 0, Mloc = NTOK, rowBase = 0;
    if (DOMAIN) {
        e       = blockIdx.z;
        Mloc    = g_cnt[e];
        rowBase = g_off[e];
        if ((int)blockIdx.y * 128 >= Mloc) return;
    }

    const float* A;
    if (MODE == 1) A = g_A + (size_t)rowBase * K;
    else           A = (DOMAIN ? g_Xg : xin) + (size_t)rowBase * K;
    const float* B    = Bbase    + (DOMAIN ? (size_t)e * K * Nd : 0);
    const float* bias = biasBase + (DOMAIN ? (size_t)e * Nd     : 0);
    const float* Xr   = DOMAIN ? g_Xg : xin;

    // A: m-major [128][16+4pad]  (pad=4 -> 20*g + t is a bank permutation)
    // B: k-major [16][128+8pad]  (pad=8 -> 8*k + n conflict-free)
    __shared__ uint32_t As[128][20];
    __shared__ uint32_t Bs[16][136];

    int tid   = threadIdx.x;
    int lane  = tid & 31;
    int warp  = tid >> 5;
    int warpM = warp >> 2;       // 0..1
    int warpN = warp & 3;        // 0..3
    int grp   = lane >> 2;       // 0..7
    int t4    = lane & 3;        // 0..3

    int rowTile = blockIdx.y * 128;
    int colTile = blockIdx.x * 128;

    float acc[4][4][4];
#pragma unroll
    for (int mi = 0; mi < 4; mi++)
#pragma unroll
        for (int ni = 0; ni < 4; ni++)
#pragma unroll
            for (int j = 0; j < 4; j++) acc[mi][ni][j] = 0.f;

    for (int kk = 0; kk < K; kk += 16) {
        // ---- stage gmem -> smem (tf32-converted) ----
#pragma unroll
        for (int i = 0; i < 2; i++) {
            int idx = tid + i * 256;          // 0..511
            // A: 128 rows x 16 k, float4 along k
            int ar = idx >> 2;                // 0..127
            int akq = (idx & 3) * 4;          // 0,4,8,12
            float4 av = make_float4(0.f, 0.f, 0.f, 0.f);
            if (rowTile + ar < Mloc)
                av = *(const float4*)(A + (size_t)(rowTile + ar) * K + kk + akq);
            As[ar][akq + 0] = f2tf32(av.x);
            As[ar][akq + 1] = f2tf32(av.y);
            As[ar][akq + 2] = f2tf32(av.z);
            As[ar][akq + 3] = f2tf32(av.w);
            // B: 16 rows x 128 n, float4 along n
            int br = idx >> 5;                // 0..15
            int bc = (idx & 31) * 4;          // 0..124
            float4 bv = *(const float4*)(B + (size_t)(kk + br) * Nd + colTile + bc);
            Bs[br][bc + 0] = f2tf32(bv.x);
            Bs[br][bc + 1] = f2tf32(bv.y);
            Bs[br][bc + 2] = f2tf32(bv.z);
            Bs[br][bc + 3] = f2tf32(bv.w);
        }
        __syncthreads();

        // ---- compute: 2 k8 steps, 4x4 mma tiles per warp ----
#pragma unroll
        for (int kb = 0; kb < 16; kb += 8) {
            uint32_t af[4][4];
            uint32_t bf[4][2];
#pragma unroll
            for (int mi = 0; mi < 4; mi++) {
                int r0 = warpM * 64 + mi * 16 + grp;
                af[mi][0] = As[r0    ][kb + t4];
                af[mi][1] = As[r0 + 8][kb + t4];
                af[mi][2] = As[r0    ][kb + t4 + 4];
                af[mi][3] = As[r0 + 8][kb + t4 + 4];
            }
#pragma unroll
            for (int ni = 0; ni < 4; ni++) {
                int c0 = warpN * 32 + ni * 8 + grp;
                bf[ni][0] = Bs[kb + t4    ][c0];
                bf[ni][1] = Bs[kb + t4 + 4][c0];
            }
#pragma unroll
            for (int mi = 0; mi < 4; mi++)
#pragma unroll
                for (int ni = 0; ni < 4; ni++)
                    mma_tf32(acc[mi][ni], af[mi], bf[ni]);
        }
        __syncthreads();
    }

    // ---------------- epilogue ----------------
#pragma unroll
    for (int mi = 0; mi < 4; mi++) {
#pragma unroll
        for (int h = 0; h < 2; h++) {
            int lr = warpM * 64 + mi * 16 + grp + h * 8;   // row within tile
            int lrT = rowTile + lr;
            if (lrT >= Mloc) continue;
            int grow = rowBase + lrT;                       // permuted-space row

#pragma unroll
            for (int ni = 0; ni < 4; ni++) {
                int col = colTile + warpN * 32 + ni * 8 + t4 * 2;
                float v0 = acc[mi][ni][h * 2 + 0];
                float v1 = acc[mi][ni][h * 2 + 1];

                if (MODE == 0) {
                    float* dst = g_A + (size_t)grow * Nd + col;
                    float a0 = v0 + bias[col];
                    float a1 = v1 + bias[col + 1];
                    dst[0] = 0.5f * a0 * (1.0f + erff(a0 * 0.70710678118654752f));
                    dst[1] = 0.5f * a1 * (1.0f + erff(a1 * 0.70710678118654752f));
                } else if (MODE == 1) {
                    float*       dst = g_H + (size_t)grow * Nd + col;
                    const float* r   = Xr  + (size_t)grow * Nd + col;
                    dst[0] = v0 + bias[col]     + r[0];
                    dst[1] = v1 + bias[col + 1] + r[1];
                } else {
                    const float* hp = g_H + (size_t)grow * Nd + col;
                    const float* xp = Xr  + (size_t)grow * Nd + col;
                    int orow = DOMAIN ? g_perm[grow] : grow;
                    float* dst = Fout + (size_t)orow * Nd + col;
                    float g0 = 1.0f / (1.0f + expf(-(v0 + bias[col])));
                    float g1 = 1.0f / (1.0f + expf(-(v1 + bias[col + 1])));
                    float o0 = g0 * hp[0] + (1.0f - g0) * xp[0];
                    float o1 = g1 * hp[1] + (1.0f - g1) * xp[1];
                    if (DOMAIN) { dst[0] += o0; dst[1] += o1; }
                    else        { dst[0]  = o0; dst[1]  = o1; }
                }
            }
        }
    }
}

// ---------------- launch -----------------------------------------------------
extern "C" void kernel_launch(void* const* d_in, const int* in_sizes, int n_in,
                              void* d_out, int out_size)
{
    const float* x   = (const float*)d_in[0];
    const int*   ids = (const int*)  d_in[1];
    const float* sW1 = (const float*)d_in[2];
    const float* sb1 = (const float*)d_in[3];
    const float* sW2 = (const float*)d_in[4];
    const float* sb2 = (const float*)d_in[5];
    const float* sWg = (const float*)d_in[6];
    const float* sbg = (const float*)d_in[7];
    const float* dW1 = (const float*)d_in[8];
    const float* db1 = (const float*)d_in[9];
    const float* dW2 = (const float*)d_in[10];
    const float* db2 = (const float*)d_in[11];
    const float* dWg = (const float*)d_in[12];
    const float* dbg = (const float*)d_in[13];
    float* out = (float*)d_out;

    // routing
    k_zero   <<<1, 32>>>();
    k_count  <<<NTOK / 256, 256>>>(ids);
    k_scan   <<<1, 32>>>();
    k_scatter<<<NTOK / 256, 256>>>(ids);
    k_gather <<<NTOK, 256>>>(x);

    dim3 blk(256);

    // shared expert (all tokens)
    gemm_k<0, false><<<dim3(FFN / 128, NTOK / 128, 1), blk>>>(x, sW1, sb1, nullptr, DIM, FFN);
    gemm_k<1, false><<<dim3(DIM / 128, NTOK / 128, 1), blk>>>(x, sW2, sb2, nullptr, FFN, DIM);
    gemm_k<2, false><<<dim3(DIM / 128, NTOK / 128, 1), blk>>>(x, sWg, sbg, out,     DIM, DIM);

    // domain experts (grouped over expert buckets; empty tiles exit immediately)
    gemm_k<0, true><<<dim3(FFN / 128, NTOK / 128, NE), blk>>>(nullptr, dW1, db1, nullptr, DIM, FFN);
    gemm_k<1, true><<<dim3(DIM / 128, NTOK / 128, NE), blk>>>(nullptr, dW2, db2, nullptr, FFN, DIM);
    gemm_k<2, true><<<dim3(DIM / 128, NTOK / 128, NE), blk>>>(nullptr, dWg, dbg, out,     DIM, DIM);
}

// round 5
// speedup vs baseline: 5.1792x; 1.8204x over previous
#include <cuda_runtime.h>
#include <cuda_bf16.h>
#include <math.h>
#include <stdint.h>

#define NTOK 8192
#define DIM  1024
#define FFN  4096
#define NE   10

typedef __nv_bfloat16 bf16;

// ---------------- scratch (device globals: no allocation allowed) ----------
__device__ bf16  g_Ab [(size_t)NTOK * FFN];   // gelu activations, bf16
__device__ float g_H  [(size_t)NTOK * DIM];   // h (fp32)
__device__ float g_Xg [(size_t)NTOK * DIM];   // gathered x, fp32 (residual/mix)
__device__ bf16  g_Xb [(size_t)NTOK * DIM];   // x bf16 (token order)
__device__ bf16  g_Xgb[(size_t)NTOK * DIM];   // gathered x bf16 (perm order)
__device__ int   g_perm[NTOK];
__device__ int   g_cnt[NE];
__device__ int   g_off[NE];
__device__ int   g_cur[NE];

// transposed bf16 weights: Wt[n*K + k] = bf16(W[k*N + n])
__device__ bf16 g_sW1t[(size_t)FFN * DIM];
__device__ bf16 g_sW2t[(size_t)DIM * FFN];
__device__ bf16 g_sWgt[(size_t)DIM * DIM];
__device__ bf16 g_dW1t[(size_t)NE * FFN * DIM];
__device__ bf16 g_dW2t[(size_t)NE * DIM * FFN];
__device__ bf16 g_dWgt[(size_t)NE * DIM * DIM];

// ---------------- PTX helpers ------------------------------------------------
__device__ __forceinline__ uint32_t smem_u32(const void* p) {
    uint32_t a;
    asm("{ .reg .u64 t; cvta.to.shared.u64 t, %1; cvt.u32.u64 %0, t; }" : "=r"(a) : "l"(p));
    return a;
}

__device__ __forceinline__ void cp16(uint32_t dst, const void* src, int srcbytes) {
    asm volatile("cp.async.cg.shared.global [%0], [%1], 16, %2;"
                 :: "r"(dst), "l"(src), "r"(srcbytes) : "memory");
}
__device__ __forceinline__ void cp_commit() {
    asm volatile("cp.async.commit_group;" ::: "memory");
}
template <int N>
__device__ __forceinline__ void cp_wait() {
    asm volatile("cp.async.wait_group %0;" :: "n"(N) : "memory");
}

__device__ __forceinline__ void ldsm_x4(uint32_t* r, uint32_t addr) {
    asm volatile("ldmatrix.sync.aligned.m8n8.x4.shared.b16 {%0,%1,%2,%3}, [%4];"
                 : "=r"(r[0]), "=r"(r[1]), "=r"(r[2]), "=r"(r[3]) : "r"(addr));
}
__device__ __forceinline__ void ldsm_x2(uint32_t* r, uint32_t addr) {
    asm volatile("ldmatrix.sync.aligned.m8n8.x2.shared.b16 {%0,%1}, [%2];"
                 : "=r"(r[0]), "=r"(r[1]) : "r"(addr));
}

__device__ __forceinline__ void mma_bf16(float* c, const uint32_t* a, const uint32_t* b) {
    asm volatile(
        "mma.sync.aligned.m16n8k16.row.col.f32.bf16.bf16.f32 "
        "{%0,%1,%2,%3},{%4,%5,%6,%7},{%8,%9},{%0,%1,%2,%3};"
        : "+f"(c[0]), "+f"(c[1]), "+f"(c[2]), "+f"(c[3])
        : "r"(a[0]), "r"(a[1]), "r"(a[2]), "r"(a[3]), "r"(b[0]), "r"(b[1]));
}

// ---------------- routing ---------------------------------------------------
__global__ void k_zero() {
    int i = threadIdx.x;
    if (i < NE) { g_cnt[i] = 0; g_cur[i] = 0; }
}
__global__ void k_count(const int* __restrict__ ids) {
    int i = blockIdx.x * blockDim.x + threadIdx.x;
    if (i < NTOK) atomicAdd(&g_cnt[ids[i]], 1);
}
__global__ void k_scan() {
    if (threadIdx.x == 0) {
        int s = 0;
        for (int e = 0; e < NE; e++) { g_off[e] = s; s += g_cnt[e]; }
    }
}
__global__ void k_scatter(const int* __restrict__ ids) {
    int i = blockIdx.x * blockDim.x + threadIdx.x;
    if (i < NTOK) {
        int e = ids[i];
        int p = g_off[e] + atomicAdd(&g_cur[e], 1);
        g_perm[p] = i;
    }
}
__global__ void k_gather(const float* __restrict__ x) {
    int p   = blockIdx.x;
    int src = g_perm[p];
    float4 v = ((const float4*)(x + (size_t)src * DIM))[threadIdx.x];
    ((float4*)(g_Xg + (size_t)p * DIM))[threadIdx.x] = v;
    union { __nv_bfloat162 h; uint32_t u; } a, b;
    a.h = __floats2bfloat162_rn(v.x, v.y);
    b.h = __floats2bfloat162_rn(v.z, v.w);
    ((uint2*)(g_Xgb + (size_t)p * DIM))[threadIdx.x] = make_uint2(a.u, b.u);
}

// ---------------- converts ---------------------------------------------------
__global__ void k_cvt_x(const float* __restrict__ x) {
    int i = blockIdx.x * blockDim.x + threadIdx.x;
    float4 v = ((const float4*)x)[i];
    union { __nv_bfloat162 h; uint32_t u; } a, b;
    a.h = __floats2bfloat162_rn(v.x, v.y);
    b.h = __floats2bfloat162_rn(v.z, v.w);
    ((uint2*)g_Xb)[i] = make_uint2(a.u, b.u);
}

// transpose + convert: Wt[n][k] = bf16(W[k][n]); which selects dst
__global__ void k_transpose(const float* __restrict__ W, int K, int N, int which) {
    bf16* Wt = which == 0 ? g_sW1t : which == 1 ? g_sW2t : which == 2 ? g_sWgt
             : which == 3 ? g_dW1t : which == 4 ? g_dW2t : g_dWgt;
    int e = blockIdx.z;
    W  += (size_t)e * K * N;
    Wt += (size_t)e * K * N;
    __shared__ float t[32][33];
    int n0 = blockIdx.x * 32, k0 = blockIdx.y * 32;
#pragma unroll
    for (int i = threadIdx.y; i < 32; i += 8)
        t[i][threadIdx.x] = W[(size_t)(k0 + i) * N + n0 + threadIdx.x];
    __syncthreads();
#pragma unroll
    for (int i = threadIdx.y; i < 32; i += 8)
        Wt[(size_t)(n0 + i) * K + k0 + threadIdx.x] = __float2bfloat16(t[threadIdx.x][i]);
}

// ---------------- bf16 tensor-core GEMM --------------------------------------
// BM=128, BN=128, BK=32, 256 threads = 8 warps (2 x 4), warp tile 64x32.
// Double-buffered cp.async staging; ldmatrix fragment loads; HMMA.16816.bf16.
// MODE 0: g_Ab = bf16(gelu(A@B + bias))
// MODE 1: g_H  = A@B + bias + xres
// MODE 2: g = sigmoid(A@B + bias); out = g*h + (1-g)*x (domain: += at perm row)
#define APAD 40              // row stride in elems (80B): conflict-free ldmatrix
#define BUFB (128 * APAD)    // elems per buffer

template <int MODE, bool DOMAIN>
__global__ void __launch_bounds__(256, 2) gemm_k(
    const float* __restrict__ xf,
    const float* __restrict__ biasBase,
    float*       __restrict__ Fout,
    int K, int Nd)
{
    int e = 0, Mloc = NTOK, rowBase = 0;
    if (DOMAIN) {
        e       = blockIdx.z;
        Mloc    = g_cnt[e];
        rowBase = g_off[e];
        if ((int)blockIdx.y * 128 >= Mloc) return;
    }

    const bf16* A;
    if (MODE == 1) A = g_Ab + (size_t)rowBase * K;
    else           A = (DOMAIN ? g_Xgb : g_Xb) + (size_t)rowBase * K;
    const bf16* Wt =
        MODE == 0 ? (DOMAIN ? g_dW1t : g_sW1t)
      : MODE == 1 ? (DOMAIN ? g_dW2t : g_sW2t)
                  : (DOMAIN ? g_dWgt : g_sWgt);
    if (DOMAIN) Wt += (size_t)e * K * Nd;
    const float* bias = biasBase + (DOMAIN ? (size_t)e * Nd : 0);
    const float* Xr   = DOMAIN ? g_Xg : xf;

    __shared__ bf16 As[2][BUFB];
    __shared__ bf16 Bs[2][BUFB];
    uint32_t asb = smem_u32(As);
    uint32_t bsb = smem_u32(Bs);

    int tid   = threadIdx.x;
    int lane  = tid & 31;
    int warp  = tid >> 5;
    int warpM = warp >> 2;        // 0..1
    int warpN = warp & 3;         // 0..3

    int rowTile = blockIdx.y * 128;
    int colTile = blockIdx.x * 128;

    // staging map: idx = tid + i*256 -> row = idx>>2 (0..127), seg = idx&3
    int srow = tid >> 2;
    int sseg = (tid & 3) * 8;     // elem offset

    // ldmatrix lane-dependent offsets (in elems)
    int aoff = (lane & 15) * APAD + ((lane >> 4) << 3);
    int boff = (lane & 7)  * APAD + (((lane >> 3) & 1) << 3);

    float acc[4][4][4];
#pragma unroll
    for (int mi = 0; mi < 4; mi++)
#pragma unroll
        for (int ni = 0; ni < 4; ni++)
#pragma unroll
            for (int j = 0; j < 4; j++) acc[mi][ni][j] = 0.f;

    // ---- prefetch first chunk into buffer 0 ----
#pragma unroll
    for (int i = 0; i < 2; i++) {
        int row = srow + i * 64;
        int av  = (rowTile + row) < Mloc ? 16 : 0;
        cp16(asb + (uint32_t)(row * APAD + sseg) * 2,
             A + (size_t)(rowTile + row) * K + sseg, av);
        cp16(bsb + (uint32_t)(row * APAD + sseg) * 2,
             Wt + (size_t)(colTile + row) * K + sseg, 16);
    }
    cp_commit();

    int buf = 0;
    for (int kk = 0; kk < K; kk += 32) {
        int nxt = kk + 32;
        if (nxt < K) {
            uint32_t dOff = (uint32_t)(buf ^ 1) * BUFB * 2;
#pragma unroll
            for (int i = 0; i < 2; i++) {
                int row = srow + i * 64;
                int av  = (rowTile + row) < Mloc ? 16 : 0;
                cp16(asb + dOff + (uint32_t)(row * APAD + sseg) * 2,
                     A + (size_t)(rowTile + row) * K + nxt + sseg, av);
                cp16(bsb + dOff + (uint32_t)(row * APAD + sseg) * 2,
                     Wt + (size_t)(colTile + row) * K + nxt + sseg, 16);
            }
            cp_commit();
            cp_wait<1>();
        } else {
            cp_wait<0>();
        }
        __syncthreads();

        uint32_t aBuf = asb + (uint32_t)buf * BUFB * 2;
        uint32_t bBuf = bsb + (uint32_t)buf * BUFB * 2;
#pragma unroll
        for (int kb = 0; kb < 32; kb += 16) {
            uint32_t af[4][4], bfr[4][2];
#pragma unroll
            for (int mi = 0; mi < 4; mi++)
                ldsm_x4(af[mi], aBuf + (uint32_t)((warpM * 64 + mi * 16) * APAD + kb + aoff) * 2);
#pragma unroll
            for (int ni = 0; ni < 4; ni++)
                ldsm_x2(bfr[ni], bBuf + (uint32_t)((warpN * 32 + ni * 8) * APAD + kb + boff) * 2);
#pragma unroll
            for (int mi = 0; mi < 4; mi++)
#pragma unroll
                for (int ni = 0; ni < 4; ni++)
                    mma_bf16(acc[mi][ni], af[mi], bfr[ni]);
        }
        __syncthreads();
        buf ^= 1;
    }

    // ---------------- epilogue ----------------
    int grp = lane >> 2;          // 0..7
    int t4  = lane & 3;           // 0..3
#pragma unroll
    for (int mi = 0; mi < 4; mi++) {
#pragma unroll
        for (int h = 0; h < 2; h++) {
            int lr  = rowTile + warpM * 64 + mi * 16 + grp + h * 8;
            if (lr >= Mloc) continue;
            int grow = rowBase + lr;

#pragma unroll
            for (int ni = 0; ni < 4; ni++) {
                int col = colTile + warpN * 32 + ni * 8 + t4 * 2;
                float v0 = acc[mi][ni][h * 2 + 0];
                float v1 = acc[mi][ni][h * 2 + 1];

                if (MODE == 0) {
                    float a0 = v0 + bias[col];
                    float a1 = v1 + bias[col + 1];
                    a0 = 0.5f * a0 * (1.0f + erff(a0 * 0.70710678118654752f));
                    a1 = 0.5f * a1 * (1.0f + erff(a1 * 0.70710678118654752f));
                    union { __nv_bfloat162 h2; uint32_t u; } cv;
                    cv.h2 = __floats2bfloat162_rn(a0, a1);
                    *(uint32_t*)(g_Ab + (size_t)grow * Nd + col) = cv.u;
                } else if (MODE == 1) {
                    float*       dst = g_H + (size_t)grow * Nd + col;
                    const float* r   = Xr  + (size_t)grow * Nd + col;
                    dst[0] = v0 + bias[col]     + r[0];
                    dst[1] = v1 + bias[col + 1] + r[1];
                } else {
                    const float* hp = g_H + (size_t)grow * Nd + col;
                    const float* xp = Xr  + (size_t)grow * Nd + col;
                    int orow = DOMAIN ? g_perm[grow] : grow;
                    float* dst = Fout + (size_t)orow * Nd + col;
                    float g0 = 1.0f / (1.0f + expf(-(v0 + bias[col])));
                    float g1 = 1.0f / (1.0f + expf(-(v1 + bias[col + 1])));
                    float o0 = g0 * hp[0] + (1.0f - g0) * xp[0];
                    float o1 = g1 * hp[1] + (1.0f - g1) * xp[1];
                    if (DOMAIN) { dst[0] += o0; dst[1] += o1; }
                    else        { dst[0]  = o0; dst[1]  = o1; }
                }
            }
        }
    }
}

// ---------------- launch -----------------------------------------------------
extern "C" void kernel_launch(void* const* d_in, const int* in_sizes, int n_in,
                              void* d_out, int out_size)
{
    const float* x   = (const float*)d_in[0];
    const int*   ids = (const int*)  d_in[1];
    const float* sW1 = (const float*)d_in[2];
    const float* sb1 = (const float*)d_in[3];
    const float* sW2 = (const float*)d_in[4];
    const float* sb2 = (const float*)d_in[5];
    const float* sWg = (const float*)d_in[6];
    const float* sbg = (const float*)d_in[7];
    const float* dW1 = (const float*)d_in[8];
    const float* db1 = (const float*)d_in[9];
    const float* dW2 = (const float*)d_in[10];
    const float* db2 = (const float*)d_in[11];
    const float* dWg = (const float*)d_in[12];
    const float* dbg = (const float*)d_in[13];
    float* out = (float*)d_out;

    // routing + converts
    k_zero   <<<1, 32>>>();
    k_count  <<<NTOK / 256, 256>>>(ids);
    k_scan   <<<1, 32>>>();
    k_scatter<<<NTOK / 256, 256>>>(ids);
    k_gather <<<NTOK, 256>>>(x);
    k_cvt_x  <<<NTOK * DIM / 4 / 256, 256>>>(x);

    dim3 tb(32, 8);
    k_transpose<<<dim3(FFN / 32, DIM / 32, 1),  tb>>>(sW1, DIM, FFN, 0);
    k_transpose<<<dim3(DIM / 32, FFN / 32, 1),  tb>>>(sW2, FFN, DIM, 1);
    k_transpose<<<dim3(DIM / 32, DIM / 32, 1),  tb>>>(sWg, DIM, DIM, 2);
    k_transpose<<<dim3(FFN / 32, DIM / 32, NE), tb>>>(dW1, DIM, FFN, 3);
    k_transpose<<<dim3(DIM / 32, FFN / 32, NE), tb>>>(dW2, FFN, DIM, 4);
    k_transpose<<<dim3(DIM / 32, DIM / 32, NE), tb>>>(dWg, DIM, DIM, 5);

    // shared expert
    gemm_k<0, false><<<dim3(FFN / 128, NTOK / 128, 1), 256>>>(x, sb1, nullptr, DIM, FFN);
    gemm_k<1, false><<<dim3(DIM / 128, NTOK / 128, 1), 256>>>(x, sb2, nullptr, FFN, DIM);
    gemm_k<2, false><<<dim3(DIM / 128, NTOK / 128, 1), 256>>>(x, sbg, out,     DIM, DIM);

    // domain experts (grouped; empty tiles bail)
    gemm_k<0, true><<<dim3(FFN / 128, NTOK / 128, NE), 256>>>(x, db1, nullptr, DIM, FFN);
    gemm_k<1, true><<<dim3(DIM / 128, NTOK / 128, NE), 256>>>(x, db2, nullptr, FFN, DIM);
    gemm_k<2, true><<<dim3(DIM / 128, NTOK / 128, NE), 256>>>(x, dbg, out,     DIM, DIM);
}